// round 9
// baseline (speedup 1.0000x reference)
#include <cuda_runtime.h>
#include <cstdint>

// Conv2d N=16,C=128,H=W=56,K=128,3x3,pad1 as 9 shifted GEMMs using
// mma.sync.m16n8k16.f32.f16.f16.f32 (base PTX).
// CTA = 64k x 112 pos (2 rows x 56 w), 128 threads (4 warps: 2m x 2row),
// grid 896, occ 4 -> finer tail quantum + cross-CTA bubble filling.
// 3-slot cp.async W ring (4KB slabs), double-buffered X (LDG->cvt->STS),
// one barrier per stage. A frags = LDS.128, B frags = LDS.64 (bank-opt).

typedef uint32_t u32;

#define X_ELEMS 3904                 // u32 half2 units: 2kk x 4lq x 4row x 122
#define W_ELEMS 1024                 // u32: [mgrp:2][mt:2][kk:2][lane:32][4]
#define XB(i)   ((i) * X_ELEMS)
#define WB(i)   (2 * X_ELEMS + (i) * W_ELEMS)
#define SMEM_BYTES ((2 * X_ELEMS + 3 * W_ELEMS) * 4)   // 43520

__device__ u32 g_Wh[36 * 2048];      // [slab:36][ktile:2][1024] fp16x2 fragments

__global__ void prep_weights(const float* __restrict__ wt) {
    int idx = blockIdx.x * 256 + threadIdx.x;
    if (idx >= 36 * 2048) return;
    int slab   = idx >> 11;
    int within = idx & 2047;
    int kt   = within >> 10;
    int vi   = within & 3;           // a-reg index a0..a3
    int lane = (within >> 2) & 31;
    int kk   = (within >> 7) & 1;
    int mt   = (within >> 8) & 1;
    int mgrp = (within >> 9) & 1;
    int cg = slab / 9, rs = slab % 9;
    int k  = kt * 64 + mgrp * 32 + mt * 16 + (lane >> 2) + (vi & 1) * 8;
    int c0 = cg * 32 + kk * 16 + (lane & 3) * 2 + (vi >> 1) * 8;
    float v0 = wt[(size_t)k * 1152 + (size_t)c0 * 9 + rs];
    float v1 = wt[(size_t)k * 1152 + (size_t)(c0 + 1) * 9 + rs];
    u32 p;
    asm("cvt.rn.f16x2.f32 %0, %1, %2;" : "=r"(p) : "f"(v1), "f"(v0));
    g_Wh[idx] = p;
}

__global__ __launch_bounds__(128, 4)
void conv_mma(const float* __restrict__ in,
              const float* __restrict__ bias,
              float* __restrict__ out)
{
    extern __shared__ u32 sm[];
    u32 sbase;
    asm("{ .reg .u64 t; cvta.to.shared.u64 t, %1; cvt.u32.u64 %0, t; }"
        : "=r"(sbase) : "l"(sm));

    const int tid = threadIdx.x;
    const int wid = tid >> 5, lid = tid & 31;
    const int lq = lid & 3, g = lid >> 2;
    const int mgrp = wid & 1;             // warp m group (32 k each)
    const int wn = wid >> 1;              // warp output row (0/1)

    // blockIdx.x = img*56 + ht*2 + kt  (k-halves of same tile adjacent)
    const int kt  = blockIdx.x & 1;
    const int ht  = (blockIdx.x >> 1) % 28;
    const int img = blockIdx.x / 56;
    const int h0  = ht * 2;
    const float* in_n = in + (size_t)img * 401408;

    float acc[2][7][4];
    #pragma unroll
    for (int mt = 0; mt < 2; mt++)
        #pragma unroll
        for (int nt = 0; nt < 7; nt++)
            #pragma unroll
            for (int q = 0; q < 4; q++) acc[mt][nt][q] = 0.f;

    // ---- X loader: LDG fp32 -> cvt.rn.f16x2 -> STS (once per element) ----
    auto loadX = [&](int cg, int xb) {
        for (int idx = tid; idx < 3712; idx += 128) {
            int wl  = idx % 58;
            int t   = idx / 58;
            int row = t & 3;
            int hi  = (t >> 2) & 1;
            int lq_ = (t >> 3) & 3;
            int kk_ = t >> 5;
            int hin = h0 - 1 + row;
            int win = wl - 1;
            int c0  = cg * 32 + kk_ * 16 + lq_ * 2 + hi * 8;
            float v0 = 0.f, v1 = 0.f;
            if (((unsigned)hin < 56u) & ((unsigned)win < 56u)) {
                const float* p = in_n + (size_t)c0 * 3136 + hin * 56 + win;
                v0 = __ldg(p);
                v1 = __ldg(p + 3136);
            }
            u32 pk;
            asm("cvt.rn.f16x2.f32 %0, %1, %2;" : "=r"(pk) : "f"(v1), "f"(v0));
            sm[XB(xb) + ((kk_ * 4 + lq_) * 4 + row) * 122 + wl * 2 + hi] = pk;
        }
    };

    // ---- async W loader: linear 4KB slab copy into ring slot ----
    auto prefW = [&](int s, int slot) {
        const u32* src = g_Wh + (size_t)s * 2048 + kt * 1024;
        const u32 dstb = sbase + WB(slot) * 4;
        #pragma unroll
        for (int j = 0; j < 2; j++) {
            int chunk = tid + j * 128;             // 0..255, 16B each
            asm volatile("cp.async.ca.shared.global [%0], [%1], 16;"
                         :: "r"(dstb + chunk * 16), "l"(src + chunk * 4)
                         : "memory");
        }
        asm volatile("cp.async.commit_group;" ::: "memory");
    };

    // ---- prologue ----
    loadX(0, 0);
    prefW(0, 0);
    prefW(1, 1);

    for (int s = 0; s < 36; s++) {
        if (s < 35) asm volatile("cp.async.wait_group 1;" ::: "memory");
        else        asm volatile("cp.async.wait_group 0;" ::: "memory");
        __syncthreads();   // W(s) + current X visible; prior consumers done

        if (s + 2 < 36) prefW(s + 2, (s + 2) % 3);
        if (s % 9 == 5 && s / 9 + 1 < 4) loadX(s / 9 + 1, (s / 9 + 1) & 1);

        const int rs = s % 9;
        const u32* Wb = sm + WB(s % 3) + mgrp * 512 + lid * 4;
        const u32* Bb = sm + XB((s / 9) & 1) + lq * 488
                        + (wn + rs / 3) * 122 + (g + rs % 3) * 2;

        #pragma unroll
        for (int kk = 0; kk < 2; kk++) {
            u32 a[2][4], b[7][2];
            #pragma unroll
            for (int mt = 0; mt < 2; mt++) {
                uint4 v = *reinterpret_cast<const uint4*>(
                              Wb + mt * 256 + kk * 128);
                a[mt][0] = v.x; a[mt][1] = v.y; a[mt][2] = v.z; a[mt][3] = v.w;
            }
            #pragma unroll
            for (int nt = 0; nt < 7; nt++) {
                uint2 v = *reinterpret_cast<const uint2*>(
                              Bb + kk * 1952 + nt * 16);
                b[nt][0] = v.x;
                b[nt][1] = v.y;
            }
            #pragma unroll
            for (int mt = 0; mt < 2; mt++)
                #pragma unroll
                for (int nt = 0; nt < 7; nt++)
                    asm volatile(
                        "mma.sync.aligned.m16n8k16.row.col.f32.f16.f16.f32 "
                        "{%0,%1,%2,%3}, {%4,%5,%6,%7}, {%8,%9}, {%0,%1,%2,%3};"
                        : "+f"(acc[mt][nt][0]), "+f"(acc[mt][nt][1]),
                          "+f"(acc[mt][nt][2]), "+f"(acc[mt][nt][3])
                        : "r"(a[mt][0]), "r"(a[mt][1]), "r"(a[mt][2]), "r"(a[mt][3]),
                          "r"(b[nt][0]), "r"(b[nt][1]));
        }
    }

    // ---- epilogue: direct STG.64 + bias ----
    #pragma unroll
    for (int mt = 0; mt < 2; mt++)
        #pragma unroll
        for (int h = 0; h < 2; h++) {
            const int k = kt * 64 + mgrp * 32 + mt * 16 + h * 8 + g;
            const float bv = __ldg(&bias[k]);
            float* op = out + (size_t)img * 401408 + (size_t)k * 3136
                        + (h0 + wn) * 56 + lq * 2;
            #pragma unroll
            for (int nt = 0; nt < 7; nt++) {
                float2 v;
                v.x = acc[mt][nt][2 * h + 0] + bv;
                v.y = acc[mt][nt][2 * h + 1] + bv;
                *reinterpret_cast<float2*>(op + nt * 8) = v;
            }
        }
}

extern "C" void kernel_launch(void* const* d_in, const int* in_sizes, int n_in,
                              void* d_out, int out_size)
{
    const float* input  = (const float*)d_in[0];
    const float* weight = (const float*)d_in[1];
    const float* bias   = (const float*)d_in[2];
    float* out = (float*)d_out;

    cudaFuncSetAttribute(conv_mma, cudaFuncAttributeMaxDynamicSharedMemorySize,
                         SMEM_BYTES);

    prep_weights<<<(36 * 2048 + 255) / 256, 256>>>(weight);
    conv_mma<<<896, 128, SMEM_BYTES>>>(input, bias, out);
}

// round 10
// speedup vs baseline: 1.0061x; 1.0061x over previous
#include <cuda_runtime.h>
#include <cstdint>

// Conv2d N=16,C=128,H=W=56,K=128,3x3,pad1 as 9 shifted GEMMs using
// mma.sync.m16n8k16.f32.f16.f16.f32 (base PTX).
// CTA = 128k x 112 pos (2 rows x 56 w), 8 warps, grid 448, occ 2.
// NO W smem: A fragments LDG.128 direct from L2-resident g_Wh,
// register double-buffered one stage ahead. Only 4 barriers total
// (X c-group boundaries); warps self-paced between them.

typedef uint32_t u32;

#define X_ELEMS 3904                 // u32 half2 units: 2kk x 4lq x 4row x 122
#define XB(i)   ((i) * X_ELEMS)
#define SMEM_BYTES (2 * X_ELEMS * 4) // 31232

__device__ u32 g_Wh[36 * 2048];      // [slab:36][mgrp:4][mt:2][kk:2][lane:32][4] fp16x2

__global__ void prep_weights(const float* __restrict__ wt) {
    int idx = blockIdx.x * 256 + threadIdx.x;
    if (idx >= 36 * 2048) return;
    int slab   = idx >> 11;
    int within = idx & 2047;
    int vi   = within & 3;           // a-reg index a0..a3
    int lane = (within >> 2) & 31;
    int kk   = (within >> 7) & 1;
    int mt   = (within >> 8) & 1;
    int mgrp = (within >> 9) & 3;
    int cg = slab / 9, rs = slab % 9;
    int k  = mgrp * 32 + mt * 16 + (lane >> 2) + (vi & 1) * 8;
    int c0 = cg * 32 + kk * 16 + (lane & 3) * 2 + (vi >> 1) * 8;
    float v0 = wt[(size_t)k * 1152 + (size_t)c0 * 9 + rs];
    float v1 = wt[(size_t)k * 1152 + (size_t)(c0 + 1) * 9 + rs];
    u32 p;
    asm("cvt.rn.f16x2.f32 %0, %1, %2;" : "=r"(p) : "f"(v1), "f"(v0));
    g_Wh[idx] = p;
}

__global__ __launch_bounds__(256, 2)
void conv_mma(const float* __restrict__ in,
              const float* __restrict__ bias,
              float* __restrict__ out)
{
    extern __shared__ u32 sm[];

    const int tid = threadIdx.x;
    const int wid = tid >> 5, lid = tid & 31;
    const int lq = lid & 3, g = lid >> 2;
    const int mgrp = wid & 3;             // warp m group (32 k each)
    const int wn = wid >> 2;              // warp output row (0/1)

    const int img = blockIdx.x / 28;
    const int h0  = (blockIdx.x % 28) * 2;
    const float* in_n = in + (size_t)img * 401408;

    float acc[2][7][4];
    #pragma unroll
    for (int mt = 0; mt < 2; mt++)
        #pragma unroll
        for (int nt = 0; nt < 7; nt++)
            #pragma unroll
            for (int q = 0; q < 4; q++) acc[mt][nt][q] = 0.f;

    // ---- X loader: LDG fp32 -> cvt.rn.f16x2 -> STS (once per element) ----
    auto loadX = [&](int cg, int xb) {
        #pragma unroll 1
        for (int idx = tid; idx < 3712; idx += 256) {
            int wl  = idx % 58;
            int t   = idx / 58;
            int row = t & 3;
            int hi  = (t >> 2) & 1;
            int lq_ = (t >> 3) & 3;
            int kk_ = t >> 5;
            int hin = h0 - 1 + row;
            int win = wl - 1;
            int c0  = cg * 32 + kk_ * 16 + lq_ * 2 + hi * 8;
            float v0 = 0.f, v1 = 0.f;
            if (((unsigned)hin < 56u) & ((unsigned)win < 56u)) {
                const float* p = in_n + (size_t)c0 * 3136 + hin * 56 + win;
                v0 = __ldg(p);
                v1 = __ldg(p + 3136);
            }
            u32 pk;
            asm("cvt.rn.f16x2.f32 %0, %1, %2;" : "=r"(pk) : "f"(v1), "f"(v0));
            sm[XB(xb) + ((kk_ * 4 + lq_) * 4 + row) * 122 + wl * 2 + hi] = pk;
        }
    };

    // ---- A fragment loader: 4x LDG.128 from L2-hot g_Wh ----
    auto ldA = [&](int s, u32 a[2][2][4]) {
        const u32* Wg = g_Wh + (size_t)s * 2048 + mgrp * 512 + lid * 4;
        #pragma unroll
        for (int mt = 0; mt < 2; mt++)
            #pragma unroll
            for (int kk = 0; kk < 2; kk++) {
                uint4 v = __ldg(reinterpret_cast<const uint4*>(
                                    Wg + mt * 256 + kk * 128));
                a[mt][kk][0] = v.x; a[mt][kk][1] = v.y;
                a[mt][kk][2] = v.z; a[mt][kk][3] = v.w;
            }
    };

    u32 aA[2][2][4], aB[2][2][4];

    // ---- prologue ----
    loadX(0, 0);
    __syncthreads();        // X(0) published
    loadX(1, 1);            // fills buf1 during group 0
    ldA(0, aA);

    #pragma unroll 2
    for (int s = 0; s < 36; s++) {
        if ((s % 9) == 0 && s > 0) {
            __syncthreads();                       // X(s/9) published; old buf free
            if (s < 27) loadX(s / 9 + 1, (s / 9 + 1) & 1);
        }

        u32 (*ac)[2][4] = (s & 1) ? aB : aA;
        u32 (*an)[2][4] = (s & 1) ? aA : aB;
        ldA(s + 1 < 36 ? s + 1 : 35, an);          // prefetch next stage's A

        const int rs = s % 9;
        const u32* Bb = sm + XB((s / 9) & 1) + lq * 488
                        + (wn + rs / 3) * 122 + (g + rs % 3) * 2;

        #pragma unroll
        for (int kk = 0; kk < 2; kk++) {
            u32 b[7][2];
            #pragma unroll
            for (int nt = 0; nt < 7; nt++) {
                uint2 v = *reinterpret_cast<const uint2*>(
                              Bb + kk * 1952 + nt * 16);
                b[nt][0] = v.x;
                b[nt][1] = v.y;
            }
            #pragma unroll
            for (int mt = 0; mt < 2; mt++)
                #pragma unroll
                for (int nt = 0; nt < 7; nt++)
                    asm volatile(
                        "mma.sync.aligned.m16n8k16.row.col.f32.f16.f16.f32 "
                        "{%0,%1,%2,%3}, {%4,%5,%6,%7}, {%8,%9}, {%0,%1,%2,%3};"
                        : "+f"(acc[mt][nt][0]), "+f"(acc[mt][nt][1]),
                          "+f"(acc[mt][nt][2]), "+f"(acc[mt][nt][3])
                        : "r"(ac[mt][kk][0]), "r"(ac[mt][kk][1]),
                          "r"(ac[mt][kk][2]), "r"(ac[mt][kk][3]),
                          "r"(b[nt][0]), "r"(b[nt][1]));
        }
    }

    // ---- epilogue: direct STG.64 + bias ----
    #pragma unroll
    for (int mt = 0; mt < 2; mt++)
        #pragma unroll
        for (int h = 0; h < 2; h++) {
            const int k = mgrp * 32 + mt * 16 + h * 8 + g;
            const float bv = __ldg(&bias[k]);
            float* op = out + (size_t)img * 401408 + (size_t)k * 3136
                        + (h0 + wn) * 56 + lq * 2;
            #pragma unroll
            for (int nt = 0; nt < 7; nt++) {
                float2 v;
                v.x = acc[mt][nt][2 * h + 0] + bv;
                v.y = acc[mt][nt][2 * h + 1] + bv;
                *reinterpret_cast<float2*>(op + nt * 8) = v;
            }
        }
}

extern "C" void kernel_launch(void* const* d_in, const int* in_sizes, int n_in,
                              void* d_out, int out_size)
{
    const float* input  = (const float*)d_in[0];
    const float* weight = (const float*)d_in[1];
    const float* bias   = (const float*)d_in[2];
    float* out = (float*)d_out;

    cudaFuncSetAttribute(conv_mma, cudaFuncAttributeMaxDynamicSharedMemorySize,
                         SMEM_BYTES);

    prep_weights<<<(36 * 2048 + 255) / 256, 256>>>(weight);
    conv_mma<<<448, 256, SMEM_BYTES>>>(input, bias, out);
}